// round 13
// baseline (speedup 1.0000x reference)
#include <cuda_runtime.h>
#include <math.h>

#define BB   16
#define CC   512
#define HWD  4096
#define BIG  (BB*CC*HWD)
#define EPSV 1e-8f
#define KTOP 12
#define SPLIT 8
#define CPS  (CC/SPLIT)          /* 64 channels per split */
#define NWRD (HWD/32)
#define GRID 1024
#define NTHR 256

// ---------------- scratch ----------------------------------------------------
__device__ float    g_p0[SPLIT*BB*HWD];
__device__ float    g_p1[SPLIT*BB*HWD];
__device__ float    g_p2[SPLIT*BB*HWD];
__device__ float    g_pred[BB*HWD];
__device__ float    g_invq[BB*HWD];
__device__ unsigned g_mfbits[BB*NWRD];
__device__ unsigned g_mbbits[BB*NWRD];
__device__ int      g_cnt[2*BB];
__device__ float    g_fgsum[BB*CC];
__device__ float    g_bgsum[BB*CC];
__device__ float    g_proto[2*BB*CC];
__device__ float    g_pnorm[2*BB];
__device__ float    g_actd[2*BB*HWD];
__device__ unsigned g_mm[4];
__device__ unsigned g_barcnt;

// ---------------- helpers ----------------------------------------------------
__device__ __forceinline__ unsigned fenc(float f) {
    unsigned u = __float_as_uint(f);
    return (u & 0x80000000u) ? ~u : (u | 0x80000000u);
}
__device__ __forceinline__ float fdec(unsigned e) {
    return (e & 0x80000000u) ? __uint_as_float(e & 0x7fffffffu)
                             : __uint_as_float(~e);
}

__device__ __forceinline__ void gbar() {
    __syncthreads();
    if (threadIdx.x == 0) {
        __threadfence();
        unsigned old = atomicAdd(&g_barcnt, 1u);
        unsigned target = (old / GRID + 1u) * GRID;
        while (*(volatile unsigned*)&g_barcnt < target) { }
        __threadfence();
    }
    __syncthreads();
}

__device__ __forceinline__ float blkSum(float v, float* sh) {
    int lane = threadIdx.x & 31, w = threadIdx.x >> 5;
#pragma unroll
    for (int o = 16; o; o >>= 1) v += __shfl_down_sync(0xffffffffu, v, o);
    if (lane == 0) sh[w] = v;
    __syncthreads();
    if (w == 0) {
        float r = (lane < 8) ? sh[lane] : 0.f;
#pragma unroll
        for (int o = 4; o; o >>= 1) r += __shfl_down_sync(0xffffffffu, r, o);
        if (lane == 0) sh[0] = r;
    }
    __syncthreads();
    float r = sh[0];
    __syncthreads();
    return r;
}

__device__ __forceinline__ unsigned blkUMin(unsigned v, unsigned* sh) {
    int lane = threadIdx.x & 31, w = threadIdx.x >> 5;
#pragma unroll
    for (int o = 16; o; o >>= 1) v = min(v, __shfl_down_sync(0xffffffffu, v, o));
    if (lane == 0) sh[w] = v;
    __syncthreads();
    if (w == 0) {
        unsigned r = (lane < 8) ? sh[lane] : 0xFFFFFFFFu;
#pragma unroll
        for (int o = 4; o; o >>= 1) r = min(r, __shfl_down_sync(0xffffffffu, r, o));
        if (lane == 0) sh[0] = r;
    }
    __syncthreads();
    unsigned r = sh[0];
    __syncthreads();
    return r;
}
__device__ __forceinline__ unsigned blkUMax(unsigned v, unsigned* sh) {
    int lane = threadIdx.x & 31, w = threadIdx.x >> 5;
#pragma unroll
    for (int o = 16; o; o >>= 1) v = max(v, __shfl_down_sync(0xffffffffu, v, o));
    if (lane == 0) sh[w] = v;
    __syncthreads();
    if (w == 0) {
        unsigned r = (lane < 8) ? sh[lane] : 0u;
#pragma unroll
        for (int o = 4; o; o >>= 1) r = max(r, __shfl_down_sync(0xffffffffu, r, o));
        if (lane == 0) sh[0] = r;
    }
    __syncthreads();
    unsigned r = sh[0];
    __syncthreads();
    return r;
}

// ---------------- reset kernel (per-launch state) ----------------------------
__global__ void k_reset() {
    int t = threadIdx.x;
    if (t == 0) g_barcnt = 0u;
    if (t < 2*BB) g_cnt[t] = 0;
    if (t < 4)   g_mm[t] = (t & 1) ? 0u : 0xFFFFFFFFu;
}

// ---------------- the persistent kernel --------------------------------------
__global__ void __launch_bounds__(NTHR, 7)
k_all(const float* __restrict__ feat, const float* __restrict__ sfp,
      const float* __restrict__ sbp, const float* __restrict__ tau,
      float* __restrict__ outp) {
    __shared__ float    s_f[CPS], s_b[CPS];
    __shared__ float    shf[32];
    __shared__ unsigned shu[32];
    __shared__ int      shc[2][8];
    __shared__ unsigned s_mfb[NWRD], s_mbb[NWRD];
    __shared__ float    sv[HWD];
    __shared__ float    rv[8];
    __shared__ int      ri[8];
    __shared__ int      sel[KTOP];
    __shared__ float    mm[4];

    int bid = blockIdx.x, tid = threadIdx.x;
    int l = tid & 31, w = tid >> 5;

    // ---------- phase 1: sim_part (1024 items) ----------
    {
        int b = bid >> 6, rest = bid & 63;
        int s = rest >> 3, chunk = rest & 7;
        if (tid < CPS) {
            s_f[tid] = sfp[b*CC + s*CPS + tid];
            s_b[tid] = sbp[b*CC + s*CPS + tid];
        }
        __syncthreads();
        const float2* fb = (const float2*)(feat + ((size_t)(b*CC + s*CPS))*HWD
                                           + (chunk << 9)) + tid;
        float d0 = 0.f, d1 = 0.f, e0 = 0.f, e1 = 0.f, q0 = 0.f, q1 = 0.f;
#pragma unroll 16
        for (int c = 0; c < CPS; c++) {
            float2 x = __ldg(&fb[(size_t)c*(HWD/2)]);
            float pf = s_f[c], pb = s_b[c];
            d0 = fmaf(x.x, pf, d0); d1 = fmaf(x.y, pf, d1);
            e0 = fmaf(x.x, pb, e0); e1 = fmaf(x.y, pb, e1);
            q0 = fmaf(x.x, x.x, q0); q1 = fmaf(x.y, x.y, q1);
        }
        int o = s*BB*HWD + b*HWD + (chunk << 9);
        ((float2*)(g_p0 + o))[tid] = make_float2(d0, d1);
        ((float2*)(g_p1 + o))[tid] = make_float2(e0, e1);
        ((float2*)(g_p2 + o))[tid] = make_float2(q0, q1);
    }
    gbar();

    // ---------- phase 2: sim_fin (256 items) ----------
    if (bid < 256) {
        int b = bid >> 4, chunk = bid & 15;
        float nf = 0.f, nb = 0.f;
        for (int c = tid; c < CC; c += NTHR) {
            float a = sfp[b*CC + c], d = sbp[b*CC + c];
            nf += a*a; nb += d*d;
        }
        nf = blkSum(nf, shf);
        nb = blkSum(nb, shf);
        float nfp = sqrtf(nf), nbp = sqrtf(nb);
        float ft  = 1.f / (1.f + expf(-tau[0]));
        float bt  = 1.f - ft;

        int p  = (chunk << 8) + tid;
        int gp = b*HWD + p;
        float dfg = 0.f, dbg = 0.f, nq = 0.f;
#pragma unroll
        for (int s = 0; s < SPLIT; s++) {
            int o = s*BB*HWD + gp;
            dfg += g_p0[o]; dbg += g_p1[o]; nq += g_p2[o];
        }
        float inv_q = 1.f / fmaxf(sqrtf(nq), EPSV);
        float cfg = dfg * inv_q / fmaxf(nfp, EPSV);
        float cbg = dbg * inv_q / fmaxf(nbp, EPSV);
        float pf  = 1.f / (1.f + expf(10.f * (cbg - cfg)));
        float pb  = 1.f / (1.f + expf(10.f * (cfg - cbg)));
        bool mfb = pf > ft;
        bool mbb = pb > bt;
        g_pred[gp] = pf;
        g_invq[gp] = inv_q;

        unsigned bf  = __ballot_sync(0xffffffffu, mfb);
        unsigned bbt = __ballot_sync(0xffffffffu, mbb);
        if (l == 0) {
            g_mfbits[b*NWRD + (chunk << 3) + w] = bf;
            g_mbbits[b*NWRD + (chunk << 3) + w] = bbt;
            shc[0][w] = __popc(bf); shc[1][w] = __popc(bbt);
        }
        __syncthreads();
        if (tid == 0) {
            int cf = 0, cb = 0;
#pragma unroll
            for (int j = 0; j < 8; j++) { cf += shc[0][j]; cb += shc[1][j]; }
            atomicAdd(&g_cnt[b],      cf);
            atomicAdd(&g_cnt[BB + b], cb);
        }
    }
    gbar();

    // ---------- phase 3: msum (1024 items) ----------
    {
        int b = bid >> 6, cgrp = bid & 63;
        if (tid < NWRD) {
            s_mfb[tid] = g_mfbits[b*NWRD + tid];
            s_mbb[tid] = g_mbbits[b*NWRD + tid];
        }
        __syncthreads();

        int c = (cgrp << 3) + w;
        const float4* row = (const float4*)(feat + ((size_t)(b*CC + c))*HWD);
        float sf0 = 0.f, sf1 = 0.f, sb0 = 0.f, sb1 = 0.f;
#pragma unroll 8
        for (int i = 0; i < 32; i++) {
            int idx = l + (i << 5);
            float4 x = __ldg(&row[idx]);
            unsigned wf = s_mfb[idx >> 3] >> ((idx & 7) << 2);
            unsigned wb = s_mbb[idx >> 3] >> ((idx & 7) << 2);
            if (wf & 1u) sf0 += x.x;
            if (wf & 2u) sf1 += x.y;
            if (wf & 4u) sf0 += x.z;
            if (wf & 8u) sf1 += x.w;
            if (wb & 1u) sb0 += x.x;
            if (wb & 2u) sb1 += x.y;
            if (wb & 4u) sb0 += x.z;
            if (wb & 8u) sb1 += x.w;
        }
        float sf = sf0 + sf1, sb = sb0 + sb1;
#pragma unroll
        for (int o = 16; o; o >>= 1) {
            sf += __shfl_down_sync(0xffffffffu, sf, o);
            sb += __shfl_down_sync(0xffffffffu, sb, o);
        }
        if (l == 0) { g_fgsum[b*CC + c] = sf; g_bgsum[b*CC + c] = sb; }
    }
    gbar();

    // ---------- phase 4: proto (32 items) ----------
    if (bid < 2*BB) {
        int b = bid >> 1, cls = bid & 1;
        int cnt = g_cnt[cls*BB + b];

        if (cnt == 0) {   // stable top-12 fallback
            for (int p = tid; p < HWD; p += NTHR) {
                float pf = g_pred[b*HWD + p];
                sv[p] = cls ? (1.f - pf) : pf;
            }
            __syncthreads();
            for (int r = 0; r < KTOP; r++) {
                float bv = -1e30f; int bi = HWD;
                for (int p = tid; p < HWD; p += NTHR) {
                    float v = sv[p];
                    if (v > bv) { bv = v; bi = p; }
                }
#pragma unroll
                for (int o = 16; o; o >>= 1) {
                    float ov = __shfl_down_sync(0xffffffffu, bv, o);
                    int   oi = __shfl_down_sync(0xffffffffu, bi, o);
                    if (ov > bv || (ov == bv && oi < bi)) { bv = ov; bi = oi; }
                }
                if (l == 0) { rv[w] = bv; ri[w] = bi; }
                __syncthreads();
                if (tid == 0) {
                    for (int j = 1; j < 8; j++)
                        if (rv[j] > bv || (rv[j] == bv && ri[j] < bi)) { bv = rv[j]; bi = ri[j]; }
                    sel[r] = bi;
                    sv[bi] = -1e30f;
                }
                __syncthreads();
            }
        }
        __syncthreads();

        float inv = (cnt > 0) ? 1.f / (float)cnt : (1.f / (float)KTOP);
        const float* sums = cls ? g_bgsum : g_fgsum;
        float n2 = 0.f;
        for (int c = tid; c < CC; c += NTHR) {
            float v;
            if (cnt > 0) {
                v = sums[b*CC + c] * inv;
            } else {
                float s = 0.f;
#pragma unroll
                for (int j = 0; j < KTOP; j++)
                    s += feat[((size_t)(b*CC + c))*HWD + sel[j]];
                v = s * inv;
            }
            g_proto[(cls*BB + b)*CC + c] = v;
            outp[BIG + cls*BB*CC + b*CC + c] = v;
            n2 += v*v;
        }
        n2 = blkSum(n2, shf);
        if (tid == 0) g_pnorm[cls*BB + b] = sqrtf(n2);
    }
    gbar();

    // ---------- phase 5: act_part (1024 items) ----------
    {
        int b = bid >> 6, rest = bid & 63;
        int s = rest >> 3, chunk = rest & 7;
        if (tid < CPS) {
            s_f[tid] = g_proto[b*CC + s*CPS + tid];
            s_b[tid] = g_proto[(BB + b)*CC + s*CPS + tid];
        }
        __syncthreads();

        const float2* fb = (const float2*)(feat + ((size_t)(b*CC + s*CPS))*HWD
                                           + (chunk << 9)) + tid;
        float d0 = 0.f, d1 = 0.f, e0 = 0.f, e1 = 0.f;
#pragma unroll 16
        for (int c = 0; c < CPS; c++) {
            float2 x = __ldg(&fb[(size_t)c*(HWD/2)]);
            float pf = s_f[c], pb = s_b[c];
            d0 = fmaf(x.x, pf, d0); d1 = fmaf(x.y, pf, d1);
            e0 = fmaf(x.x, pb, e0); e1 = fmaf(x.y, pb, e1);
        }
        int o = s*BB*HWD + b*HWD + (chunk << 9);
        ((float2*)(g_p0 + o))[tid] = make_float2(d0, d1);
        ((float2*)(g_p1 + o))[tid] = make_float2(e0, e1);
    }
    gbar();

    // ---------- phase 6: act_fin (128 items) ----------
    if (bid < BB*8) {
        int b = bid >> 3, chunk = bid & 7;
        int gp2 = (b*HWD + (chunk << 9)) >> 1;

        float2 dfg = make_float2(0.f, 0.f), dbg = make_float2(0.f, 0.f);
#pragma unroll
        for (int s = 0; s < SPLIT; s++) {
            int o2 = (s*BB*HWD >> 1) + gp2 + tid;
            float2 a = ((const float2*)g_p0)[o2];
            float2 d = ((const float2*)g_p1)[o2];
            dfg.x += a.x; dfg.y += a.y;
            dbg.x += d.x; dbg.y += d.y;
        }
        float2 inv_q = ((const float2*)g_invq)[gp2 + tid];
        float rfp = 1.f / fmaxf(g_pnorm[b], EPSV);
        float rbp = 1.f / fmaxf(g_pnorm[BB + b], EPSV);
        float ca0 = dfg.x * inv_q.x * rfp, ca1 = dfg.y * inv_q.y * rfp;
        float cd0 = dbg.x * inv_q.x * rbp, cd1 = dbg.y * inv_q.y * rbp;
        float4 pk; pk.x = ca0; pk.y = cd0; pk.z = ca1; pk.w = cd1;
        ((float4*)g_actd)[gp2 + tid] = pk;

        unsigned amn = blkUMin(min(fenc(ca0), fenc(ca1)), shu);
        unsigned amx = blkUMax(max(fenc(ca0), fenc(ca1)), shu);
        unsigned dmn = blkUMin(min(fenc(cd0), fenc(cd1)), shu);
        unsigned dmx = blkUMax(max(fenc(cd0), fenc(cd1)), shu);
        if (tid == 0) {
            atomicMin(&g_mm[0], amn);
            atomicMax(&g_mm[1], amx);
            atomicMin(&g_mm[2], dmn);
            atomicMax(&g_mm[3], dmx);
        }
    }
    gbar();

    // ---------- phase 7: blend output (32 chunks per block) ----------
    {
        if (tid < 4) mm[tid] = fdec(g_mm[tid]);
        __syncthreads();
        float amin = mm[0], ira = 1.f / (mm[1] - mm[0]);
        float dmin = mm[2], ird = 1.f / (mm[3] - mm[2]);

#pragma unroll 4
        for (int j = 0; j < 32; j++) {
            size_t i4 = (((size_t)j*GRID + bid) << 8) | tid;
            size_t e  = i4 << 2;
            int b = (int)(e >> 21);
            int p = (int)(e & (HWD - 1));
            float4 x = __ldg(&((const float4*)feat)[i4]);
            int ai = (b*HWD + p) >> 1;
            float4 s0 = ((const float4*)g_actd)[ai];
            float4 s1 = ((const float4*)g_actd)[ai + 1];
            float4 o;
            o.x = x.x * ((s0.x - amin)*ira + 1.f - (s0.y - dmin)*ird);
            o.y = x.y * ((s0.z - amin)*ira + 1.f - (s0.w - dmin)*ird);
            o.z = x.z * ((s1.x - amin)*ira + 1.f - (s1.y - dmin)*ird);
            o.w = x.w * ((s1.z - amin)*ira + 1.f - (s1.w - dmin)*ird);
            ((float4*)outp)[i4] = o;
        }
    }
}

// ---------------- launch -----------------------------------------------------
extern "C" void kernel_launch(void* const* d_in, const int* in_sizes, int n_in,
                              void* d_out, int out_size) {
    const float* sfp  = (const float*)d_in[0];
    const float* sbp  = (const float*)d_in[1];
    const float* feat = (const float*)d_in[2];
    const float* tau  = (const float*)d_in[3];
    float* outp = (float*)d_out;

    k_reset<<<1, 64>>>();
    k_all<<<GRID, NTHR>>>(feat, sfp, sbp, tau, outp);
    (void)in_sizes; (void)n_in; (void)out_size;
}

// round 14
// speedup vs baseline: 1.0724x; 1.0724x over previous
#include <cuda_runtime.h>
#include <math.h>

#define BB   16
#define CC   512
#define HWD  4096
#define BIG  (BB*CC*HWD)
#define EPSV 1e-8f
#define KTOP 12
#define SPLIT 8
#define CPS  (CC/SPLIT)          /* 64 channels per split */
#define NWRD (HWD/32)            /* 128 mask words per batch */

// ---------------- scratch ----------------------------------------------------
__device__ float    g_p0[SPLIT*BB*HWD];
__device__ float    g_p1[SPLIT*BB*HWD];
__device__ float    g_p2[SPLIT*BB*HWD];
__device__ float    g_pred[BB*HWD];
__device__ float    g_invq[BB*HWD];
__device__ unsigned g_mfbits[BB*NWRD];
__device__ unsigned g_mbbits[BB*NWRD];
__device__ int      g_cnt[2*BB];
__device__ float    g_fgsum[BB*CC];
__device__ float    g_bgsum[BB*CC];
__device__ float    g_proto[2*BB*CC];
__device__ float    g_pnorm[2*BB];
__device__ float    g_actd[2*BB*HWD];     // interleaved (ca,cd)
__device__ unsigned g_mm[4];

// ---------------- helpers ----------------------------------------------------
__device__ __forceinline__ unsigned fenc(float f) {
    unsigned u = __float_as_uint(f);
    return (u & 0x80000000u) ? ~u : (u | 0x80000000u);
}
__device__ __forceinline__ float fdec(unsigned e) {
    return (e & 0x80000000u) ? __uint_as_float(e & 0x7fffffffu)
                             : __uint_as_float(~e);
}

__device__ __forceinline__ float blkSum(float v, float* sh) {
    int lane = threadIdx.x & 31, w = threadIdx.x >> 5;
#pragma unroll
    for (int o = 16; o; o >>= 1) v += __shfl_down_sync(0xffffffffu, v, o);
    if (lane == 0) sh[w] = v;
    __syncthreads();
    if (w == 0) {
        float r = (lane < 8) ? sh[lane] : 0.f;
#pragma unroll
        for (int o = 4; o; o >>= 1) r += __shfl_down_sync(0xffffffffu, r, o);
        if (lane == 0) sh[0] = r;
    }
    __syncthreads();
    float r = sh[0];
    __syncthreads();
    return r;
}

__device__ __forceinline__ unsigned blkUMin(unsigned v, unsigned* sh) {
    int lane = threadIdx.x & 31, w = threadIdx.x >> 5;
#pragma unroll
    for (int o = 16; o; o >>= 1) v = min(v, __shfl_down_sync(0xffffffffu, v, o));
    if (lane == 0) sh[w] = v;
    __syncthreads();
    if (w == 0) {
        unsigned r = (lane < 8) ? sh[lane] : 0xFFFFFFFFu;
#pragma unroll
        for (int o = 4; o; o >>= 1) r = min(r, __shfl_down_sync(0xffffffffu, r, o));
        if (lane == 0) sh[0] = r;
    }
    __syncthreads();
    unsigned r = sh[0];
    __syncthreads();
    return r;
}
__device__ __forceinline__ unsigned blkUMax(unsigned v, unsigned* sh) {
    int lane = threadIdx.x & 31, w = threadIdx.x >> 5;
#pragma unroll
    for (int o = 16; o; o >>= 1) v = max(v, __shfl_down_sync(0xffffffffu, v, o));
    if (lane == 0) sh[w] = v;
    __syncthreads();
    if (w == 0) {
        unsigned r = (lane < 8) ? sh[lane] : 0u;
#pragma unroll
        for (int o = 4; o; o >>= 1) r = max(r, __shfl_down_sync(0xffffffffu, r, o));
        if (lane == 0) sh[0] = r;
    }
    __syncthreads();
    unsigned r = sh[0];
    __syncthreads();
    return r;
}

// ------------ k1: partial dots vs support protos (split-C=8, float2) ---------
__global__ __launch_bounds__(256)
void k_sim_part(const float* __restrict__ feat, const float* __restrict__ sfp,
                const float* __restrict__ sbp) {
    __shared__ float s_f[CPS], s_b[CPS];
    int b = blockIdx.x >> 6, rest = blockIdx.x & 63;
    int s = rest >> 3, chunk = rest & 7;
    int tid = threadIdx.x;

    if (blockIdx.x == 0) {
        if (tid < 2*BB) g_cnt[tid] = 0;
        if (tid < 4)    g_mm[tid] = (tid & 1) ? 0u : 0xFFFFFFFFu;
    }
    if (tid < CPS) {
        s_f[tid] = sfp[b*CC + s*CPS + tid];
        s_b[tid] = sbp[b*CC + s*CPS + tid];
    }
    __syncthreads();

    const float2* fb = (const float2*)(feat + ((size_t)(b*CC + s*CPS))*HWD
                                       + (chunk << 9)) + tid;
    float d0 = 0.f, d1 = 0.f, e0 = 0.f, e1 = 0.f, q0 = 0.f, q1 = 0.f;
#pragma unroll 16
    for (int c = 0; c < CPS; c++) {
        float2 x = __ldg(&fb[(size_t)c*(HWD/2)]);
        float pf = s_f[c], pb = s_b[c];
        d0 = fmaf(x.x, pf, d0); d1 = fmaf(x.y, pf, d1);
        e0 = fmaf(x.x, pb, e0); e1 = fmaf(x.y, pb, e1);
        q0 = fmaf(x.x, x.x, q0); q1 = fmaf(x.y, x.y, q1);
    }
    int o = s*BB*HWD + b*HWD + (chunk << 9);
    ((float2*)(g_p0 + o))[tid] = make_float2(d0, d1);
    ((float2*)(g_p1 + o))[tid] = make_float2(e0, e1);
    ((float2*)(g_p2 + o))[tid] = make_float2(q0, q1);
}

// ------------ k2: finalize pred/bitmasks/counts (grid 256) -------------------
__global__ __launch_bounds__(256)
void k_sim_fin(const float* __restrict__ sfp, const float* __restrict__ sbp,
               const float* __restrict__ tau) {
    __shared__ float sh[32];
    __shared__ int   shc[2][8];
    int b = blockIdx.x >> 4, chunk = blockIdx.x & 15;
    int tid = threadIdx.x;

    float nf = 0.f, nb = 0.f;
    for (int c = tid; c < CC; c += 256) {
        float a = sfp[b*CC + c], d = sbp[b*CC + c];
        nf += a*a; nb += d*d;
    }
    nf = blkSum(nf, sh);
    nb = blkSum(nb, sh);
    float nfp = sqrtf(nf), nbp = sqrtf(nb);
    float ft  = 1.f / (1.f + expf(-tau[0]));
    float bt  = 1.f - ft;

    int p  = (chunk << 8) + tid;
    int gp = b*HWD + p;
    float dfg = 0.f, dbg = 0.f, nq = 0.f;
#pragma unroll
    for (int s = 0; s < SPLIT; s++) {
        int o = s*BB*HWD + gp;
        dfg += g_p0[o]; dbg += g_p1[o]; nq += g_p2[o];
    }
    float inv_q = 1.f / fmaxf(sqrtf(nq), EPSV);
    float cfg = dfg * inv_q / fmaxf(nfp, EPSV);
    float cbg = dbg * inv_q / fmaxf(nbp, EPSV);
    float pf  = 1.f / (1.f + expf(10.f * (cbg - cfg)));
    float pb  = 1.f / (1.f + expf(10.f * (cfg - cbg)));
    bool mfb = pf > ft;
    bool mbb = pb > bt;
    g_pred[gp] = pf;
    g_invq[gp] = inv_q;

    unsigned bf  = __ballot_sync(0xffffffffu, mfb);
    unsigned bbt = __ballot_sync(0xffffffffu, mbb);
    int w = tid >> 5;
    if ((tid & 31) == 0) {
        g_mfbits[b*NWRD + (chunk << 3) + w] = bf;
        g_mbbits[b*NWRD + (chunk << 3) + w] = bbt;
        shc[0][w] = __popc(bf); shc[1][w] = __popc(bbt);
    }
    __syncthreads();
    if (tid == 0) {
        int cf = 0, cb = 0;
#pragma unroll
        for (int j = 0; j < 8; j++) { cf += shc[0][j]; cb += shc[1][j]; }
        atomicAdd(&g_cnt[b],      cf);
        atomicAdd(&g_cnt[BB + b], cb);
    }
}

// ------------ k3: masked channel sums (2 warps/channel, grid 2048) -----------
__global__ __launch_bounds__(256)
void k_msum(const float* __restrict__ feat) {
    __shared__ unsigned s_mfb[NWRD], s_mbb[NWRD];
    __shared__ float s_sf[8], s_sb[8];
    int b = blockIdx.x >> 7, cgrp = blockIdx.x & 127;  // 128 groups of 4 channels
    int tid = threadIdx.x, w = tid >> 5, l = tid & 31;

    if (tid < NWRD) {
        s_mfb[tid] = g_mfbits[b*NWRD + tid];
        s_mbb[tid] = g_mbbits[b*NWRD + tid];
    }
    __syncthreads();

    int c    = (cgrp << 2) + (w >> 1);
    int half = w & 1;                       // each warp does half a row
    const float4* row = (const float4*)(feat + ((size_t)(b*CC + c))*HWD);
    float sf0 = 0.f, sf1 = 0.f, sb0 = 0.f, sb1 = 0.f;
#pragma unroll 8
    for (int i = 0; i < 16; i++) {
        int idx = (half << 9) + l + (i << 5);   // float4 index within row
        float4 x = __ldg(&row[idx]);
        unsigned wf = s_mfb[idx >> 3] >> ((idx & 7) << 2);
        unsigned wb = s_mbb[idx >> 3] >> ((idx & 7) << 2);
        if (wf & 1u) sf0 += x.x;
        if (wf & 2u) sf1 += x.y;
        if (wf & 4u) sf0 += x.z;
        if (wf & 8u) sf1 += x.w;
        if (wb & 1u) sb0 += x.x;
        if (wb & 2u) sb1 += x.y;
        if (wb & 4u) sb0 += x.z;
        if (wb & 8u) sb1 += x.w;
    }
    float sf = sf0 + sf1, sb = sb0 + sb1;
#pragma unroll
    for (int o = 16; o; o >>= 1) {
        sf += __shfl_down_sync(0xffffffffu, sf, o);
        sb += __shfl_down_sync(0xffffffffu, sb, o);
    }
    if (l == 0) { s_sf[w] = sf; s_sb[w] = sb; }
    __syncthreads();
    if (tid < 4) {
        g_fgsum[b*CC + (cgrp << 2) + tid] = s_sf[2*tid] + s_sf[2*tid + 1];
        g_bgsum[b*CC + (cgrp << 2) + tid] = s_sb[2*tid] + s_sb[2*tid + 1];
    }
}

// ------------ k4: prototypes --------------------------------------------------
__global__ __launch_bounds__(256)
void k_proto(const float* __restrict__ feat, float* __restrict__ outp) {
    __shared__ float sv[HWD];
    __shared__ int   sel[KTOP];
    __shared__ float shf[32];
    __shared__ float rv[8];
    __shared__ int   ri[8];
    int b = blockIdx.x >> 1, cls = blockIdx.x & 1;
    int tid = threadIdx.x;
    int cnt = g_cnt[cls*BB + b];

    if (cnt == 0) {   // stable top-12 fallback
        for (int p = tid; p < HWD; p += 256) {
            float pf = g_pred[b*HWD + p];
            sv[p] = cls ? (1.f - pf) : pf;
        }
        __syncthreads();
        for (int r = 0; r < KTOP; r++) {
            float bv = -1e30f; int bi = HWD;
            for (int p = tid; p < HWD; p += 256) {
                float v = sv[p];
                if (v > bv) { bv = v; bi = p; }
            }
            int lane = tid & 31, w = tid >> 5;
#pragma unroll
            for (int o = 16; o; o >>= 1) {
                float ov = __shfl_down_sync(0xffffffffu, bv, o);
                int   oi = __shfl_down_sync(0xffffffffu, bi, o);
                if (ov > bv || (ov == bv && oi < bi)) { bv = ov; bi = oi; }
            }
            if (lane == 0) { rv[w] = bv; ri[w] = bi; }
            __syncthreads();
            if (tid == 0) {
                for (int j = 1; j < 8; j++)
                    if (rv[j] > bv || (rv[j] == bv && ri[j] < bi)) { bv = rv[j]; bi = ri[j]; }
                sel[r] = bi;
                sv[bi] = -1e30f;
            }
            __syncthreads();
        }
    }
    __syncthreads();

    float inv = (cnt > 0) ? 1.f / (float)cnt : (1.f / (float)KTOP);
    const float* sums = cls ? g_bgsum : g_fgsum;
    float n2 = 0.f;
    for (int c = tid; c < CC; c += 256) {
        float v;
        if (cnt > 0) {
            v = sums[b*CC + c] * inv;
        } else {
            float s = 0.f;
#pragma unroll
            for (int j = 0; j < KTOP; j++)
                s += feat[((size_t)(b*CC + c))*HWD + sel[j]];
            v = s * inv;
        }
        g_proto[(cls*BB + b)*CC + c] = v;
        outp[BIG + cls*BB*CC + b*CC + c] = v;
        n2 += v*v;
    }
    n2 = blkSum(n2, shf);
    if (tid == 0) g_pnorm[cls*BB + b] = sqrtf(n2);
}

// ------------ k5: partial dots vs query protos (split-C=8, float2) -----------
__global__ __launch_bounds__(256)
void k_act_part(const float* __restrict__ feat) {
    __shared__ float s_f[CPS], s_b[CPS];
    int b = blockIdx.x >> 6, rest = blockIdx.x & 63;
    int s = rest >> 3, chunk = rest & 7;
    int tid = threadIdx.x;

    if (tid < CPS) {
        s_f[tid] = g_proto[b*CC + s*CPS + tid];
        s_b[tid] = g_proto[(BB + b)*CC + s*CPS + tid];
    }
    __syncthreads();

    const float2* fb = (const float2*)(feat + ((size_t)(b*CC + s*CPS))*HWD
                                       + (chunk << 9)) + tid;
    float d0 = 0.f, d1 = 0.f, e0 = 0.f, e1 = 0.f;
#pragma unroll 16
    for (int c = 0; c < CPS; c++) {
        float2 x = __ldg(&fb[(size_t)c*(HWD/2)]);
        float pf = s_f[c], pb = s_b[c];
        d0 = fmaf(x.x, pf, d0); d1 = fmaf(x.y, pf, d1);
        e0 = fmaf(x.x, pb, e0); e1 = fmaf(x.y, pb, e1);
    }
    int o = s*BB*HWD + b*HWD + (chunk << 9);
    ((float2*)(g_p0 + o))[tid] = make_float2(d0, d1);
    ((float2*)(g_p1 + o))[tid] = make_float2(e0, e1);
}

// ------------ k6: finalize act/deact + minmax (float2, grid 128) -------------
__global__ __launch_bounds__(256)
void k_act_fin() {
    __shared__ unsigned shu[32];
    int b = blockIdx.x >> 3, chunk = blockIdx.x & 7;
    int tid = threadIdx.x;
    int gp2 = (b*HWD + (chunk << 9)) >> 1;

    float2 dfg = make_float2(0.f, 0.f), dbg = make_float2(0.f, 0.f);
#pragma unroll
    for (int s = 0; s < SPLIT; s++) {
        int o2 = (s*BB*HWD >> 1) + gp2 + tid;
        float2 a = ((const float2*)g_p0)[o2];
        float2 d = ((const float2*)g_p1)[o2];
        dfg.x += a.x; dfg.y += a.y;
        dbg.x += d.x; dbg.y += d.y;
    }
    float2 inv_q = ((const float2*)g_invq)[gp2 + tid];
    float rfp = 1.f / fmaxf(g_pnorm[b], EPSV);
    float rbp = 1.f / fmaxf(g_pnorm[BB + b], EPSV);
    float ca0 = dfg.x * inv_q.x * rfp, ca1 = dfg.y * inv_q.y * rfp;
    float cd0 = dbg.x * inv_q.x * rbp, cd1 = dbg.y * inv_q.y * rbp;
    float4 pk; pk.x = ca0; pk.y = cd0; pk.z = ca1; pk.w = cd1;
    ((float4*)g_actd)[gp2 + tid] = pk;

    unsigned amn = blkUMin(min(fenc(ca0), fenc(ca1)), shu);
    unsigned amx = blkUMax(max(fenc(ca0), fenc(ca1)), shu);
    unsigned dmn = blkUMin(min(fenc(cd0), fenc(cd1)), shu);
    unsigned dmx = blkUMax(max(fenc(cd0), fenc(cd1)), shu);
    if (tid == 0) {
        atomicMin(&g_mm[0], amn);
        atomicMax(&g_mm[1], amx);
        atomicMin(&g_mm[2], dmn);
        atomicMax(&g_mm[3], dmx);
    }
}

// ------------ k7: blend output ------------------------------------------------
__global__ __launch_bounds__(256)
void k_out(const float* __restrict__ feat, float* __restrict__ outp) {
    __shared__ float mm[4];
    if (threadIdx.x < 4) mm[threadIdx.x] = fdec(g_mm[threadIdx.x]);
    __syncthreads();
    float amin = mm[0], ira = 1.f / (mm[1] - mm[0]);
    float dmin = mm[2], ird = 1.f / (mm[3] - mm[2]);

    size_t i4 = (size_t)blockIdx.x * 256 + threadIdx.x;
    size_t e  = i4 << 2;
    int b = (int)(e >> 21);
    int p = (int)(e & (HWD - 1));
    float4 x = __ldg(&((const float4*)feat)[i4]);
    int ai = (b*HWD + p) >> 1;
    float4 s0 = ((const float4*)g_actd)[ai];
    float4 s1 = ((const float4*)g_actd)[ai + 1];
    float4 o;
    o.x = x.x * ((s0.x - amin)*ira + 1.f - (s0.y - dmin)*ird);
    o.y = x.y * ((s0.z - amin)*ira + 1.f - (s0.w - dmin)*ird);
    o.z = x.z * ((s1.x - amin)*ira + 1.f - (s1.y - dmin)*ird);
    o.w = x.w * ((s1.z - amin)*ira + 1.f - (s1.w - dmin)*ird);
    ((float4*)outp)[i4] = o;
}

// ---------------- launch -----------------------------------------------------
extern "C" void kernel_launch(void* const* d_in, const int* in_sizes, int n_in,
                              void* d_out, int out_size) {
    const float* sfp  = (const float*)d_in[0];
    const float* sbp  = (const float*)d_in[1];
    const float* feat = (const float*)d_in[2];
    const float* tau  = (const float*)d_in[3];
    float* outp = (float*)d_out;

    k_sim_part<<<BB*8*SPLIT, 256>>>(feat, sfp, sbp);
    k_sim_fin <<<BB*16, 256>>>(sfp, sbp, tau);
    k_msum    <<<BB*128, 256>>>(feat);
    k_proto   <<<2*BB, 256>>>(feat, outp);
    k_act_part<<<BB*8*SPLIT, 256>>>(feat);
    k_act_fin <<<BB*8, 256>>>();
    k_out     <<<BIG/4/256, 256>>>(feat, outp);
    (void)in_sizes; (void)n_in; (void)out_size;
}

// round 15
// speedup vs baseline: 1.1313x; 1.0549x over previous
#include <cuda_runtime.h>
#include <math.h>

#define BB   16
#define CC   512
#define HWD  4096
#define BIG  (BB*CC*HWD)
#define EPSV 1e-8f
#define KTOP 12
#define SPLIT 8
#define CPS  (CC/SPLIT)          /* 64 channels per split */
#define NWRD (HWD/32)            /* 128 mask words per batch */

// ---------------- scratch ----------------------------------------------------
__device__ float    g_p0[SPLIT*BB*HWD];
__device__ float    g_p1[SPLIT*BB*HWD];
__device__ float    g_p2[SPLIT*BB*HWD];
__device__ float    g_pred[BB*HWD];
__device__ float    g_invq[BB*HWD];
__device__ unsigned g_mfbits[BB*NWRD];
__device__ unsigned g_mbbits[BB*NWRD];
__device__ int      g_cnt[2*BB];
__device__ float    g_fgsum[BB*CC];
__device__ float    g_bgsum[BB*CC];
__device__ float    g_proto[2*BB*CC];
__device__ float    g_pnorm[2*BB];
__device__ float    g_actd[2*BB*HWD];     // interleaved (ca,cd)
__device__ unsigned g_mm[4];

// ---------------- helpers ----------------------------------------------------
__device__ __forceinline__ unsigned fenc(float f) {
    unsigned u = __float_as_uint(f);
    return (u & 0x80000000u) ? ~u : (u | 0x80000000u);
}
__device__ __forceinline__ float fdec(unsigned e) {
    return (e & 0x80000000u) ? __uint_as_float(e & 0x7fffffffu)
                             : __uint_as_float(~e);
}

__device__ __forceinline__ float blkSum(float v, float* sh) {
    int lane = threadIdx.x & 31, w = threadIdx.x >> 5;
#pragma unroll
    for (int o = 16; o; o >>= 1) v += __shfl_down_sync(0xffffffffu, v, o);
    if (lane == 0) sh[w] = v;
    __syncthreads();
    if (w == 0) {
        float r = (lane < 8) ? sh[lane] : 0.f;
#pragma unroll
        for (int o = 4; o; o >>= 1) r += __shfl_down_sync(0xffffffffu, r, o);
        if (lane == 0) sh[0] = r;
    }
    __syncthreads();
    float r = sh[0];
    __syncthreads();
    return r;
}

__device__ __forceinline__ unsigned blkUMin(unsigned v, unsigned* sh) {
    int lane = threadIdx.x & 31, w = threadIdx.x >> 5;
#pragma unroll
    for (int o = 16; o; o >>= 1) v = min(v, __shfl_down_sync(0xffffffffu, v, o));
    if (lane == 0) sh[w] = v;
    __syncthreads();
    if (w == 0) {
        unsigned r = (lane < 8) ? sh[lane] : 0xFFFFFFFFu;
#pragma unroll
        for (int o = 4; o; o >>= 1) r = min(r, __shfl_down_sync(0xffffffffu, r, o));
        if (lane == 0) sh[0] = r;
    }
    __syncthreads();
    unsigned r = sh[0];
    __syncthreads();
    return r;
}
__device__ __forceinline__ unsigned blkUMax(unsigned v, unsigned* sh) {
    int lane = threadIdx.x & 31, w = threadIdx.x >> 5;
#pragma unroll
    for (int o = 16; o; o >>= 1) v = max(v, __shfl_down_sync(0xffffffffu, v, o));
    if (lane == 0) sh[w] = v;
    __syncthreads();
    if (w == 0) {
        unsigned r = (lane < 8) ? sh[lane] : 0u;
#pragma unroll
        for (int o = 4; o; o >>= 1) r = max(r, __shfl_down_sync(0xffffffffu, r, o));
        if (lane == 0) sh[0] = r;
    }
    __syncthreads();
    unsigned r = sh[0];
    __syncthreads();
    return r;
}

// ------------ k1: partial dots vs support protos (split-C=8, float2) ---------
__global__ __launch_bounds__(256)
void k_sim_part(const float* __restrict__ feat, const float* __restrict__ sfp,
                const float* __restrict__ sbp) {
    __shared__ float s_f[CPS], s_b[CPS];
    int b = blockIdx.x >> 6, rest = blockIdx.x & 63;
    int s = rest >> 3, chunk = rest & 7;
    int tid = threadIdx.x;

    if (blockIdx.x == 0) {
        if (tid < 2*BB) g_cnt[tid] = 0;
        if (tid < 4)    g_mm[tid] = (tid & 1) ? 0u : 0xFFFFFFFFu;
    }
    if (tid < CPS) {
        s_f[tid] = sfp[b*CC + s*CPS + tid];
        s_b[tid] = sbp[b*CC + s*CPS + tid];
    }
    __syncthreads();

    const float2* fb = (const float2*)(feat + ((size_t)(b*CC + s*CPS))*HWD
                                       + (chunk << 9)) + tid;
    float d0 = 0.f, d1 = 0.f, e0 = 0.f, e1 = 0.f, q0 = 0.f, q1 = 0.f;
#pragma unroll 16
    for (int c = 0; c < CPS; c++) {
        float2 x = __ldg(&fb[(size_t)c*(HWD/2)]);
        float pf = s_f[c], pb = s_b[c];
        d0 = fmaf(x.x, pf, d0); d1 = fmaf(x.y, pf, d1);
        e0 = fmaf(x.x, pb, e0); e1 = fmaf(x.y, pb, e1);
        q0 = fmaf(x.x, x.x, q0); q1 = fmaf(x.y, x.y, q1);
    }
    int o = s*BB*HWD + b*HWD + (chunk << 9);
    ((float2*)(g_p0 + o))[tid] = make_float2(d0, d1);
    ((float2*)(g_p1 + o))[tid] = make_float2(e0, e1);
    ((float2*)(g_p2 + o))[tid] = make_float2(q0, q1);
}

// ------------ k2: finalize pred/bitmasks/counts (grid 256) -------------------
__global__ __launch_bounds__(256)
void k_sim_fin(const float* __restrict__ sfp, const float* __restrict__ sbp,
               const float* __restrict__ tau) {
    __shared__ float sh[32];
    __shared__ int   shc[2][8];
    int b = blockIdx.x >> 4, chunk = blockIdx.x & 15;
    int tid = threadIdx.x;

    float nf = 0.f, nb = 0.f;
    for (int c = tid; c < CC; c += 256) {
        float a = sfp[b*CC + c], d = sbp[b*CC + c];
        nf += a*a; nb += d*d;
    }
    nf = blkSum(nf, sh);
    nb = blkSum(nb, sh);
    float nfp = sqrtf(nf), nbp = sqrtf(nb);
    float ft  = 1.f / (1.f + expf(-tau[0]));
    float bt  = 1.f - ft;

    int p  = (chunk << 8) + tid;
    int gp = b*HWD + p;
    float dfg = 0.f, dbg = 0.f, nq = 0.f;
#pragma unroll
    for (int s = 0; s < SPLIT; s++) {
        int o = s*BB*HWD + gp;
        dfg += g_p0[o]; dbg += g_p1[o]; nq += g_p2[o];
    }
    float inv_q = 1.f / fmaxf(sqrtf(nq), EPSV);
    float cfg = dfg * inv_q / fmaxf(nfp, EPSV);
    float cbg = dbg * inv_q / fmaxf(nbp, EPSV);
    float pf  = 1.f / (1.f + expf(10.f * (cbg - cfg)));
    float pb  = 1.f / (1.f + expf(10.f * (cfg - cbg)));
    bool mfb = pf > ft;
    bool mbb = pb > bt;
    g_pred[gp] = pf;
    g_invq[gp] = inv_q;

    unsigned bf  = __ballot_sync(0xffffffffu, mfb);
    unsigned bbt = __ballot_sync(0xffffffffu, mbb);
    int w = tid >> 5;
    if ((tid & 31) == 0) {
        g_mfbits[b*NWRD + (chunk << 3) + w] = bf;
        g_mbbits[b*NWRD + (chunk << 3) + w] = bbt;
        shc[0][w] = __popc(bf); shc[1][w] = __popc(bbt);
    }
    __syncthreads();
    if (tid == 0) {
        int cf = 0, cb = 0;
#pragma unroll
        for (int j = 0; j < 8; j++) { cf += shc[0][j]; cb += shc[1][j]; }
        atomicAdd(&g_cnt[b],      cf);
        atomicAdd(&g_cnt[BB + b], cb);
    }
}

// ------------ k3: masked channel sums (warp-per-channel, bitmask) ------------
__global__ __launch_bounds__(256)
void k_msum(const float* __restrict__ feat) {
    __shared__ unsigned s_mfb[NWRD], s_mbb[NWRD];
    int b = blockIdx.x >> 6, cgrp = blockIdx.x & 63;
    int tid = threadIdx.x, w = tid >> 5, l = tid & 31;

    if (tid < NWRD) {
        s_mfb[tid] = g_mfbits[b*NWRD + tid];
        s_mbb[tid] = g_mbbits[b*NWRD + tid];
    }
    __syncthreads();

    int c = (cgrp << 3) + w;
    const float4* row = (const float4*)(feat + ((size_t)(b*CC + c))*HWD);
    float sf0 = 0.f, sf1 = 0.f, sb0 = 0.f, sb1 = 0.f;
#pragma unroll 8
    for (int i = 0; i < 32; i++) {
        int idx = l + (i << 5);
        float4 x = __ldg(&row[idx]);
        unsigned wf = s_mfb[idx >> 3] >> ((idx & 7) << 2);
        unsigned wb = s_mbb[idx >> 3] >> ((idx & 7) << 2);
        if (wf & 1u) sf0 += x.x;
        if (wf & 2u) sf1 += x.y;
        if (wf & 4u) sf0 += x.z;
        if (wf & 8u) sf1 += x.w;
        if (wb & 1u) sb0 += x.x;
        if (wb & 2u) sb1 += x.y;
        if (wb & 4u) sb0 += x.z;
        if (wb & 8u) sb1 += x.w;
    }
    float sf = sf0 + sf1, sb = sb0 + sb1;
#pragma unroll
    for (int o = 16; o; o >>= 1) {
        sf += __shfl_down_sync(0xffffffffu, sf, o);
        sb += __shfl_down_sync(0xffffffffu, sb, o);
    }
    if (l == 0) { g_fgsum[b*CC + c] = sf; g_bgsum[b*CC + c] = sb; }
}

// ------------ k4: prototypes --------------------------------------------------
__global__ __launch_bounds__(256)
void k_proto(const float* __restrict__ feat, float* __restrict__ outp) {
    __shared__ float sv[HWD];
    __shared__ int   sel[KTOP];
    __shared__ float shf[32];
    __shared__ float rv[8];
    __shared__ int   ri[8];
    int b = blockIdx.x >> 1, cls = blockIdx.x & 1;
    int tid = threadIdx.x;
    int cnt = g_cnt[cls*BB + b];

    if (cnt == 0) {   // stable top-12 fallback
        for (int p = tid; p < HWD; p += 256) {
            float pf = g_pred[b*HWD + p];
            sv[p] = cls ? (1.f - pf) : pf;
        }
        __syncthreads();
        for (int r = 0; r < KTOP; r++) {
            float bv = -1e30f; int bi = HWD;
            for (int p = tid; p < HWD; p += 256) {
                float v = sv[p];
                if (v > bv) { bv = v; bi = p; }
            }
            int lane = tid & 31, w = tid >> 5;
#pragma unroll
            for (int o = 16; o; o >>= 1) {
                float ov = __shfl_down_sync(0xffffffffu, bv, o);
                int   oi = __shfl_down_sync(0xffffffffu, bi, o);
                if (ov > bv || (ov == bv && oi < bi)) { bv = ov; bi = oi; }
            }
            if (lane == 0) { rv[w] = bv; ri[w] = bi; }
            __syncthreads();
            if (tid == 0) {
                for (int j = 1; j < 8; j++)
                    if (rv[j] > bv || (rv[j] == bv && ri[j] < bi)) { bv = rv[j]; bi = ri[j]; }
                sel[r] = bi;
                sv[bi] = -1e30f;
            }
            __syncthreads();
        }
    }
    __syncthreads();

    float inv = (cnt > 0) ? 1.f / (float)cnt : (1.f / (float)KTOP);
    const float* sums = cls ? g_bgsum : g_fgsum;
    float n2 = 0.f;
    for (int c = tid; c < CC; c += 256) {
        float v;
        if (cnt > 0) {
            v = sums[b*CC + c] * inv;
        } else {
            float s = 0.f;
#pragma unroll
            for (int j = 0; j < KTOP; j++)
                s += feat[((size_t)(b*CC + c))*HWD + sel[j]];
            v = s * inv;
        }
        g_proto[(cls*BB + b)*CC + c] = v;
        outp[BIG + cls*BB*CC + b*CC + c] = v;
        n2 += v*v;
    }
    n2 = blkSum(n2, shf);
    if (tid == 0) g_pnorm[cls*BB + b] = sqrtf(n2);
}

// ------------ k5: partial dots vs query protos (split-C=8, float2) -----------
__global__ __launch_bounds__(256)
void k_act_part(const float* __restrict__ feat) {
    __shared__ float s_f[CPS], s_b[CPS];
    int b = blockIdx.x >> 6, rest = blockIdx.x & 63;
    int s = rest >> 3, chunk = rest & 7;
    int tid = threadIdx.x;

    if (tid < CPS) {
        s_f[tid] = g_proto[b*CC + s*CPS + tid];
        s_b[tid] = g_proto[(BB + b)*CC + s*CPS + tid];
    }
    __syncthreads();

    const float2* fb = (const float2*)(feat + ((size_t)(b*CC + s*CPS))*HWD
                                       + (chunk << 9)) + tid;
    float d0 = 0.f, d1 = 0.f, e0 = 0.f, e1 = 0.f;
#pragma unroll 16
    for (int c = 0; c < CPS; c++) {
        float2 x = __ldg(&fb[(size_t)c*(HWD/2)]);
        float pf = s_f[c], pb = s_b[c];
        d0 = fmaf(x.x, pf, d0); d1 = fmaf(x.y, pf, d1);
        e0 = fmaf(x.x, pb, e0); e1 = fmaf(x.y, pb, e1);
    }
    int o = s*BB*HWD + b*HWD + (chunk << 9);
    ((float2*)(g_p0 + o))[tid] = make_float2(d0, d1);
    ((float2*)(g_p1 + o))[tid] = make_float2(e0, e1);
}

// ------------ k6: finalize act/deact + minmax (float2, grid 128) -------------
__global__ __launch_bounds__(256)
void k_act_fin() {
    __shared__ unsigned shu[32];
    int b = blockIdx.x >> 3, chunk = blockIdx.x & 7;
    int tid = threadIdx.x;
    int gp2 = (b*HWD + (chunk << 9)) >> 1;

    float2 dfg = make_float2(0.f, 0.f), dbg = make_float2(0.f, 0.f);
#pragma unroll
    for (int s = 0; s < SPLIT; s++) {
        int o2 = (s*BB*HWD >> 1) + gp2 + tid;
        float2 a = ((const float2*)g_p0)[o2];
        float2 d = ((const float2*)g_p1)[o2];
        dfg.x += a.x; dfg.y += a.y;
        dbg.x += d.x; dbg.y += d.y;
    }
    float2 inv_q = ((const float2*)g_invq)[gp2 + tid];
    float rfp = 1.f / fmaxf(g_pnorm[b], EPSV);
    float rbp = 1.f / fmaxf(g_pnorm[BB + b], EPSV);
    float ca0 = dfg.x * inv_q.x * rfp, ca1 = dfg.y * inv_q.y * rfp;
    float cd0 = dbg.x * inv_q.x * rbp, cd1 = dbg.y * inv_q.y * rbp;
    float4 pk; pk.x = ca0; pk.y = cd0; pk.z = ca1; pk.w = cd1;
    ((float4*)g_actd)[gp2 + tid] = pk;

    unsigned amn = blkUMin(min(fenc(ca0), fenc(ca1)), shu);
    unsigned amx = blkUMax(max(fenc(ca0), fenc(ca1)), shu);
    unsigned dmn = blkUMin(min(fenc(cd0), fenc(cd1)), shu);
    unsigned dmx = blkUMax(max(fenc(cd0), fenc(cd1)), shu);
    if (tid == 0) {
        atomicMin(&g_mm[0], amn);
        atomicMax(&g_mm[1], amx);
        atomicMin(&g_mm[2], dmn);
        atomicMax(&g_mm[3], dmx);
    }
}

// ------------ k7: blend output (streaming loads/stores) ----------------------
__global__ __launch_bounds__(256)
void k_out(const float* __restrict__ feat, float* __restrict__ outp) {
    __shared__ float mm[4];
    if (threadIdx.x < 4) mm[threadIdx.x] = fdec(g_mm[threadIdx.x]);
    __syncthreads();
    float amin = mm[0], ira = 1.f / (mm[1] - mm[0]);
    float dmin = mm[2], ird = 1.f / (mm[3] - mm[2]);

    size_t i4 = (size_t)blockIdx.x * 256 + threadIdx.x;
    size_t e  = i4 << 2;
    int b = (int)(e >> 21);
    int p = (int)(e & (HWD - 1));
    float4 x = __ldcs(&((const float4*)feat)[i4]);       // evict-first: last use
    int ai = (b*HWD + p) >> 1;
    float4 s0 = ((const float4*)g_actd)[ai];
    float4 s1 = ((const float4*)g_actd)[ai + 1];
    float4 o;
    o.x = x.x * ((s0.x - amin)*ira + 1.f - (s0.y - dmin)*ird);
    o.y = x.y * ((s0.z - amin)*ira + 1.f - (s0.w - dmin)*ird);
    o.z = x.z * ((s1.x - amin)*ira + 1.f - (s1.y - dmin)*ird);
    o.w = x.w * ((s1.z - amin)*ira + 1.f - (s1.w - dmin)*ird);
    __stcs(&((float4*)outp)[i4], o);                     // streaming store
}

// ---------------- launch -----------------------------------------------------
extern "C" void kernel_launch(void* const* d_in, const int* in_sizes, int n_in,
                              void* d_out, int out_size) {
    const float* sfp  = (const float*)d_in[0];
    const float* sbp  = (const float*)d_in[1];
    const float* feat = (const float*)d_in[2];
    const float* tau  = (const float*)d_in[3];
    float* outp = (float*)d_out;

    k_sim_part<<<BB*8*SPLIT, 256>>>(feat, sfp, sbp);
    k_sim_fin <<<BB*16, 256>>>(sfp, sbp, tau);
    k_msum    <<<BB*64, 256>>>(feat);
    k_proto   <<<2*BB, 256>>>(feat, outp);
    k_act_part<<<BB*8*SPLIT, 256>>>(feat);
    k_act_fin <<<BB*8, 256>>>();
    k_out     <<<BIG/4/256, 256>>>(feat, outp);
    (void)in_sizes; (void)n_in; (void)out_size;
}

// round 16
// speedup vs baseline: 1.1445x; 1.0117x over previous
#include <cuda_runtime.h>
#include <math.h>

#define BB   16
#define CC   512
#define HWD  4096
#define BIG  (BB*CC*HWD)
#define EPSV 1e-8f
#define KTOP 12
#define SPLIT 8
#define CPS  (CC/SPLIT)          /* 64 channels per split */
#define NWRD (HWD/32)            /* 128 mask words per batch */
#define NGRP (HWD/4)             /* 1024 float4 groups per batch */

// ---------------- scratch ----------------------------------------------------
__device__ float    g_p0[SPLIT*BB*HWD];
__device__ float    g_p1[SPLIT*BB*HWD];
__device__ float    g_p2[SPLIT*BB*HWD];
__device__ float    g_pred[BB*HWD];
__device__ float    g_invq[BB*HWD];
__device__ unsigned g_mfbits[BB*NWRD];
__device__ unsigned g_mbbits[BB*NWRD];
__device__ int      g_cnt[2*BB];
__device__ float    g_fgsum[BB*CC];
__device__ float    g_bgsum[BB*CC];
__device__ float    g_proto[2*BB*CC];
__device__ float    g_pnorm[2*BB];
__device__ float    g_actd[2*BB*HWD];     // interleaved (ca,cd)
__device__ unsigned g_mm[4];

// ---------------- helpers ----------------------------------------------------
__device__ __forceinline__ unsigned fenc(float f) {
    unsigned u = __float_as_uint(f);
    return (u & 0x80000000u) ? ~u : (u | 0x80000000u);
}
__device__ __forceinline__ float fdec(unsigned e) {
    return (e & 0x80000000u) ? __uint_as_float(e & 0x7fffffffu)
                             : __uint_as_float(~e);
}

__device__ __forceinline__ float blkSum(float v, float* sh) {
    int lane = threadIdx.x & 31, w = threadIdx.x >> 5;
#pragma unroll
    for (int o = 16; o; o >>= 1) v += __shfl_down_sync(0xffffffffu, v, o);
    if (lane == 0) sh[w] = v;
    __syncthreads();
    if (w == 0) {
        float r = (lane < 8) ? sh[lane] : 0.f;
#pragma unroll
        for (int o = 4; o; o >>= 1) r += __shfl_down_sync(0xffffffffu, r, o);
        if (lane == 0) sh[0] = r;
    }
    __syncthreads();
    float r = sh[0];
    __syncthreads();
    return r;
}

__device__ __forceinline__ unsigned blkUMin(unsigned v, unsigned* sh) {
    int lane = threadIdx.x & 31, w = threadIdx.x >> 5;
#pragma unroll
    for (int o = 16; o; o >>= 1) v = min(v, __shfl_down_sync(0xffffffffu, v, o));
    if (lane == 0) sh[w] = v;
    __syncthreads();
    if (w == 0) {
        unsigned r = (lane < 8) ? sh[lane] : 0xFFFFFFFFu;
#pragma unroll
        for (int o = 4; o; o >>= 1) r = min(r, __shfl_down_sync(0xffffffffu, r, o));
        if (lane == 0) sh[0] = r;
    }
    __syncthreads();
    unsigned r = sh[0];
    __syncthreads();
    return r;
}
__device__ __forceinline__ unsigned blkUMax(unsigned v, unsigned* sh) {
    int lane = threadIdx.x & 31, w = threadIdx.x >> 5;
#pragma unroll
    for (int o = 16; o; o >>= 1) v = max(v, __shfl_down_sync(0xffffffffu, v, o));
    if (lane == 0) sh[w] = v;
    __syncthreads();
    if (w == 0) {
        unsigned r = (lane < 8) ? sh[lane] : 0u;
#pragma unroll
        for (int o = 4; o; o >>= 1) r = max(r, __shfl_down_sync(0xffffffffu, r, o));
        if (lane == 0) sh[0] = r;
    }
    __syncthreads();
    unsigned r = sh[0];
    __syncthreads();
    return r;
}

// ------------ k1: partial dots vs support protos (split-C=8, float2) ---------
__global__ __launch_bounds__(256)
void k_sim_part(const float* __restrict__ feat, const float* __restrict__ sfp,
                const float* __restrict__ sbp) {
    __shared__ float s_f[CPS], s_b[CPS];
    int b = blockIdx.x >> 6, rest = blockIdx.x & 63;
    int s = rest >> 3, chunk = rest & 7;
    int tid = threadIdx.x;

    if (blockIdx.x == 0) {
        if (tid < 2*BB) g_cnt[tid] = 0;
        if (tid < 4)    g_mm[tid] = (tid & 1) ? 0u : 0xFFFFFFFFu;
    }
    if (tid < CPS) {
        s_f[tid] = sfp[b*CC + s*CPS + tid];
        s_b[tid] = sbp[b*CC + s*CPS + tid];
    }
    __syncthreads();

    const float2* fb = (const float2*)(feat + ((size_t)(b*CC + s*CPS))*HWD
                                       + (chunk << 9)) + tid;
    float d0 = 0.f, d1 = 0.f, e0 = 0.f, e1 = 0.f, q0 = 0.f, q1 = 0.f;
#pragma unroll 16
    for (int c = 0; c < CPS; c++) {
        float2 x = __ldg(&fb[(size_t)c*(HWD/2)]);
        float pf = s_f[c], pb = s_b[c];
        d0 = fmaf(x.x, pf, d0); d1 = fmaf(x.y, pf, d1);
        e0 = fmaf(x.x, pb, e0); e1 = fmaf(x.y, pb, e1);
        q0 = fmaf(x.x, x.x, q0); q1 = fmaf(x.y, x.y, q1);
    }
    int o = s*BB*HWD + b*HWD + (chunk << 9);
    ((float2*)(g_p0 + o))[tid] = make_float2(d0, d1);
    ((float2*)(g_p1 + o))[tid] = make_float2(e0, e1);
    ((float2*)(g_p2 + o))[tid] = make_float2(q0, q1);
}

// ------------ k2: finalize pred/bitmasks/counts (grid 256) -------------------
__global__ __launch_bounds__(256)
void k_sim_fin(const float* __restrict__ sfp, const float* __restrict__ sbp,
               const float* __restrict__ tau) {
    __shared__ float sh[32];
    __shared__ int   shc[2][8];
    int b = blockIdx.x >> 4, chunk = blockIdx.x & 15;
    int tid = threadIdx.x;

    float nf = 0.f, nb = 0.f;
    for (int c = tid; c < CC; c += 256) {
        float a = sfp[b*CC + c], d = sbp[b*CC + c];
        nf += a*a; nb += d*d;
    }
    nf = blkSum(nf, sh);
    nb = blkSum(nb, sh);
    float nfp = sqrtf(nf), nbp = sqrtf(nb);
    float ft  = 1.f / (1.f + expf(-tau[0]));
    float bt  = 1.f - ft;

    int p  = (chunk << 8) + tid;
    int gp = b*HWD + p;
    float dfg = 0.f, dbg = 0.f, nq = 0.f;
#pragma unroll
    for (int s = 0; s < SPLIT; s++) {
        int o = s*BB*HWD + gp;
        dfg += g_p0[o]; dbg += g_p1[o]; nq += g_p2[o];
    }
    float inv_q = 1.f / fmaxf(sqrtf(nq), EPSV);
    float cfg = dfg * inv_q / fmaxf(nfp, EPSV);
    float cbg = dbg * inv_q / fmaxf(nbp, EPSV);
    float pf  = 1.f / (1.f + expf(10.f * (cbg - cfg)));
    float pb  = 1.f / (1.f + expf(10.f * (cfg - cbg)));
    bool mfb = pf > ft;
    bool mbb = pb > bt;
    g_pred[gp] = pf;
    g_invq[gp] = inv_q;

    unsigned bf  = __ballot_sync(0xffffffffu, mfb);
    unsigned bbt = __ballot_sync(0xffffffffu, mbb);
    int w = tid >> 5;
    if ((tid & 31) == 0) {
        g_mfbits[b*NWRD + (chunk << 3) + w] = bf;
        g_mbbits[b*NWRD + (chunk << 3) + w] = bbt;
        shc[0][w] = __popc(bf); shc[1][w] = __popc(bbt);
    }
    __syncthreads();
    if (tid == 0) {
        int cf = 0, cb = 0;
#pragma unroll
        for (int j = 0; j < 8; j++) { cf += shc[0][j]; cb += shc[1][j]; }
        atomicAdd(&g_cnt[b],      cf);
        atomicAdd(&g_cnt[BB + b], cb);
    }
}

// ------------ k3: masked channel sums (combined mask bytes, unroll 16) -------
__global__ __launch_bounds__(256)
void k_msum(const float* __restrict__ feat) {
    __shared__ unsigned char s_comb[NGRP];   // 1 byte per float4 group
    int b = blockIdx.x >> 6, cgrp = blockIdx.x & 63;
    int tid = threadIdx.x, w = tid >> 5, l = tid & 31;

    if (tid < NWRD) {
        unsigned mf = g_mfbits[b*NWRD + tid];
        unsigned mb = g_mbbits[b*NWRD + tid];
#pragma unroll
        for (int j = 0; j < 8; j++) {
            unsigned wf = (mf >> (4*j)) & 0xFu;
            unsigned wb = (mb >> (4*j)) & 0xFu;
            s_comb[8*tid + j] = (unsigned char)(wf | (wb << 4));
        }
    }
    __syncthreads();

    int c = (cgrp << 3) + w;
    const float4* row = (const float4*)(feat + ((size_t)(b*CC + c))*HWD);
    float sf0 = 0.f, sf1 = 0.f, sb0 = 0.f, sb1 = 0.f;
#pragma unroll 16
    for (int i = 0; i < 32; i++) {
        int idx = l + (i << 5);
        float4 x = __ldg(&row[idx]);
        unsigned m = s_comb[idx];
        if (m & 1u)   sf0 += x.x;
        if (m & 2u)   sf1 += x.y;
        if (m & 4u)   sf0 += x.z;
        if (m & 8u)   sf1 += x.w;
        if (m & 16u)  sb0 += x.x;
        if (m & 32u)  sb1 += x.y;
        if (m & 64u)  sb0 += x.z;
        if (m & 128u) sb1 += x.w;
    }
    float sf = sf0 + sf1, sb = sb0 + sb1;
#pragma unroll
    for (int o = 16; o; o >>= 1) {
        sf += __shfl_down_sync(0xffffffffu, sf, o);
        sb += __shfl_down_sync(0xffffffffu, sb, o);
    }
    if (l == 0) { g_fgsum[b*CC + c] = sf; g_bgsum[b*CC + c] = sb; }
}

// ------------ k4: prototypes --------------------------------------------------
__global__ __launch_bounds__(256)
void k_proto(const float* __restrict__ feat, float* __restrict__ outp) {
    __shared__ float sv[HWD];
    __shared__ int   sel[KTOP];
    __shared__ float shf[32];
    __shared__ float rv[8];
    __shared__ int   ri[8];
    int b = blockIdx.x >> 1, cls = blockIdx.x & 1;
    int tid = threadIdx.x;
    int cnt = g_cnt[cls*BB + b];

    if (cnt == 0) {   // stable top-12 fallback
        for (int p = tid; p < HWD; p += 256) {
            float pf = g_pred[b*HWD + p];
            sv[p] = cls ? (1.f - pf) : pf;
        }
        __syncthreads();
        for (int r = 0; r < KTOP; r++) {
            float bv = -1e30f; int bi = HWD;
            for (int p = tid; p < HWD; p += 256) {
                float v = sv[p];
                if (v > bv) { bv = v; bi = p; }
            }
            int lane = tid & 31, w = tid >> 5;
#pragma unroll
            for (int o = 16; o; o >>= 1) {
                float ov = __shfl_down_sync(0xffffffffu, bv, o);
                int   oi = __shfl_down_sync(0xffffffffu, bi, o);
                if (ov > bv || (ov == bv && oi < bi)) { bv = ov; bi = oi; }
            }
            if (lane == 0) { rv[w] = bv; ri[w] = bi; }
            __syncthreads();
            if (tid == 0) {
                for (int j = 1; j < 8; j++)
                    if (rv[j] > bv || (rv[j] == bv && ri[j] < bi)) { bv = rv[j]; bi = ri[j]; }
                sel[r] = bi;
                sv[bi] = -1e30f;
            }
            __syncthreads();
        }
    }
    __syncthreads();

    float inv = (cnt > 0) ? 1.f / (float)cnt : (1.f / (float)KTOP);
    const float* sums = cls ? g_bgsum : g_fgsum;
    float n2 = 0.f;
    for (int c = tid; c < CC; c += 256) {
        float v;
        if (cnt > 0) {
            v = sums[b*CC + c] * inv;
        } else {
            float s = 0.f;
#pragma unroll
            for (int j = 0; j < KTOP; j++)
                s += feat[((size_t)(b*CC + c))*HWD + sel[j]];
            v = s * inv;
        }
        g_proto[(cls*BB + b)*CC + c] = v;
        outp[BIG + cls*BB*CC + b*CC + c] = v;
        n2 += v*v;
    }
    n2 = blkSum(n2, shf);
    if (tid == 0) g_pnorm[cls*BB + b] = sqrtf(n2);
}

// ------------ k5: partial dots vs query protos (split-C=8, float2) -----------
__global__ __launch_bounds__(256)
void k_act_part(const float* __restrict__ feat) {
    __shared__ float s_f[CPS], s_b[CPS];
    int b = blockIdx.x >> 6, rest = blockIdx.x & 63;
    int s = rest >> 3, chunk = rest & 7;
    int tid = threadIdx.x;

    if (tid < CPS) {
        s_f[tid] = g_proto[b*CC + s*CPS + tid];
        s_b[tid] = g_proto[(BB + b)*CC + s*CPS + tid];
    }
    __syncthreads();

    const float2* fb = (const float2*)(feat + ((size_t)(b*CC + s*CPS))*HWD
                                       + (chunk << 9)) + tid;
    float d0 = 0.f, d1 = 0.f, e0 = 0.f, e1 = 0.f;
#pragma unroll 16
    for (int c = 0; c < CPS; c++) {
        float2 x = __ldg(&fb[(size_t)c*(HWD/2)]);
        float pf = s_f[c], pb = s_b[c];
        d0 = fmaf(x.x, pf, d0); d1 = fmaf(x.y, pf, d1);
        e0 = fmaf(x.x, pb, e0); e1 = fmaf(x.y, pb, e1);
    }
    int o = s*BB*HWD + b*HWD + (chunk << 9);
    ((float2*)(g_p0 + o))[tid] = make_float2(d0, d1);
    ((float2*)(g_p1 + o))[tid] = make_float2(e0, e1);
}

// ------------ k6: finalize act/deact + minmax (float2, grid 128) -------------
__global__ __launch_bounds__(256)
void k_act_fin() {
    __shared__ unsigned shu[32];
    int b = blockIdx.x >> 3, chunk = blockIdx.x & 7;
    int tid = threadIdx.x;
    int gp2 = (b*HWD + (chunk << 9)) >> 1;

    float2 dfg = make_float2(0.f, 0.f), dbg = make_float2(0.f, 0.f);
#pragma unroll
    for (int s = 0; s < SPLIT; s++) {
        int o2 = (s*BB*HWD >> 1) + gp2 + tid;
        float2 a = ((const float2*)g_p0)[o2];
        float2 d = ((const float2*)g_p1)[o2];
        dfg.x += a.x; dfg.y += a.y;
        dbg.x += d.x; dbg.y += d.y;
    }
    float2 inv_q = ((const float2*)g_invq)[gp2 + tid];
    float rfp = 1.f / fmaxf(g_pnorm[b], EPSV);
    float rbp = 1.f / fmaxf(g_pnorm[BB + b], EPSV);
    float ca0 = dfg.x * inv_q.x * rfp, ca1 = dfg.y * inv_q.y * rfp;
    float cd0 = dbg.x * inv_q.x * rbp, cd1 = dbg.y * inv_q.y * rbp;
    float4 pk; pk.x = ca0; pk.y = cd0; pk.z = ca1; pk.w = cd1;
    ((float4*)g_actd)[gp2 + tid] = pk;

    unsigned amn = blkUMin(min(fenc(ca0), fenc(ca1)), shu);
    unsigned amx = blkUMax(max(fenc(ca0), fenc(ca1)), shu);
    unsigned dmn = blkUMin(min(fenc(cd0), fenc(cd1)), shu);
    unsigned dmx = blkUMax(max(fenc(cd0), fenc(cd1)), shu);
    if (tid == 0) {
        atomicMin(&g_mm[0], amn);
        atomicMax(&g_mm[1], amx);
        atomicMin(&g_mm[2], dmn);
        atomicMax(&g_mm[3], dmx);
    }
}

// ------------ k7: blend output (streaming loads/stores) ----------------------
__global__ __launch_bounds__(256)
void k_out(const float* __restrict__ feat, float* __restrict__ outp) {
    __shared__ float mm[4];
    if (threadIdx.x < 4) mm[threadIdx.x] = fdec(g_mm[threadIdx.x]);
    __syncthreads();
    float amin = mm[0], ira = 1.f / (mm[1] - mm[0]);
    float dmin = mm[2], ird = 1.f / (mm[3] - mm[2]);

    size_t i4 = (size_t)blockIdx.x * 256 + threadIdx.x;
    size_t e  = i4 << 2;
    int b = (int)(e >> 21);
    int p = (int)(e & (HWD - 1));
    float4 x = __ldcs(&((const float4*)feat)[i4]);
    int ai = (b*HWD + p) >> 1;
    float4 s0 = ((const float4*)g_actd)[ai];
    float4 s1 = ((const float4*)g_actd)[ai + 1];
    float4 o;
    o.x = x.x * ((s0.x - amin)*ira + 1.f - (s0.y - dmin)*ird);
    o.y = x.y * ((s0.z - amin)*ira + 1.f - (s0.w - dmin)*ird);
    o.z = x.z * ((s1.x - amin)*ira + 1.f - (s1.y - dmin)*ird);
    o.w = x.w * ((s1.z - amin)*ira + 1.f - (s1.w - dmin)*ird);
    __stcs(&((float4*)outp)[i4], o);
}

// ---------------- launch -----------------------------------------------------
extern "C" void kernel_launch(void* const* d_in, const int* in_sizes, int n_in,
                              void* d_out, int out_size) {
    const float* sfp  = (const float*)d_in[0];
    const float* sbp  = (const float*)d_in[1];
    const float* feat = (const float*)d_in[2];
    const float* tau  = (const float*)d_in[3];
    float* outp = (float*)d_out;

    k_sim_part<<<BB*8*SPLIT, 256>>>(feat, sfp, sbp);
    k_sim_fin <<<BB*16, 256>>>(sfp, sbp, tau);
    k_msum    <<<BB*64, 256>>>(feat);
    k_proto   <<<2*BB, 256>>>(feat, outp);
    k_act_part<<<BB*8*SPLIT, 256>>>(feat);
    k_act_fin <<<BB*8, 256>>>();
    k_out     <<<BIG/4/256, 256>>>(feat, outp);
    (void)in_sizes; (void)n_in; (void)out_size;
}